// round 1
// baseline (speedup 1.0000x reference)
#include <cuda_runtime.h>

// Problem constants
#define NPTS        8192
#define BROWS       4096
#define KTOT        (NPTS * 3)            // 24576 floats per row
#define K4          (KTOT / 4)            // 6144 float4 per row

// Main kernel config
#define GRID_MAIN    152                  // one persistent CTA per SM (GB300: 152 SMs)
#define THREADS_MAIN 512
#define NWARPS       (THREADS_MAIN / 32)  // 16
#define NTILES       3
#define TILE_K4      (K4 / NTILES)        // 2048 float4 per tile
#define UNROLL       (TILE_K4 / THREADS_MAIN) // 4 float4 per thread per tile
#define MAX_LROWS    ((BROWS + GRID_MAIN - 1) / GRID_MAIN) // 27

// Precomputed flattened weights, SoA by output index j:
// g_wf[j][3n+i] = (M^T M)[j][i] for point n.  288 KB static device scratch.
__device__ float g_wf[3][KTOT];

__device__ __forceinline__ float softplusf(float x) {
    // numerically stable softplus
    return fmaxf(x, 0.0f) + log1pf(expf(-fabsf(x)));
}

// ---------------------------------------------------------------------------
// Kernel 1: build W = M^T M per integration point, expand to SoA flat layout.
// 8192 points, trivial cost.
// ---------------------------------------------------------------------------
__global__ void symm_prep_kernel(const float* __restrict__ weight) {
    int n = blockIdx.x * blockDim.x + threadIdx.x;
    if (n >= NPTS) return;

    const float* w = weight + n * 6;
    float a = softplusf(w[0]);   // M[0][0]
    float b = w[1];              // M[0][1]
    float c = w[2];              // M[0][2]
    float d = softplusf(w[3]);   // M[1][1]
    float e = w[4];              // M[1][2]
    float f = softplusf(w[5]);   // M[2][2]

    // M^T M (symmetric 3x3)
    float m00 = a * a;
    float m01 = a * b;
    float m02 = a * c;
    float m11 = b * b + d * d;
    float m12 = b * c + d * e;
    float m22 = c * c + e * e + f * f;

    int k = 3 * n;
    // j = 0 row of W
    g_wf[0][k + 0] = m00; g_wf[0][k + 1] = m01; g_wf[0][k + 2] = m02;
    // j = 1 row
    g_wf[1][k + 0] = m01; g_wf[1][k + 1] = m11; g_wf[1][k + 2] = m12;
    // j = 2 row
    g_wf[2][k + 0] = m02; g_wf[2][k + 1] = m12; g_wf[2][k + 2] = m22;
}

// ---------------------------------------------------------------------------
// Kernel 2: out[b, j] = sum_k x[b, k] * g_wf[j][k] + NPTS * bias[j]
//
// Persistent blocks; W held in REGISTERS per K-tile (loaded from global once
// per tile per thread), so the 4096-row reuse of W costs zero L2 bandwidth
// per row.  x streamed once with coalesced LDG.128 + evict-first (__ldcs).
// Warp-shuffle reduction -> warp-private smem partials -> one syncthreads.
// ---------------------------------------------------------------------------
__global__ void __launch_bounds__(THREADS_MAIN, 1)
symm_main_kernel(const float* __restrict__ x,
                 const float* __restrict__ bias,
                 float* __restrict__ out) {
    __shared__ float part[MAX_LROWS][NWARPS][3];

    const int tid  = threadIdx.x;
    const int wid  = tid >> 5;
    const int lane = tid & 31;
    const int bid  = blockIdx.x;

    const float4* __restrict__ x4  = reinterpret_cast<const float4*>(x);
    const float4* __restrict__ wf0 = reinterpret_cast<const float4*>(g_wf[0]);
    const float4* __restrict__ wf1 = reinterpret_cast<const float4*>(g_wf[1]);
    const float4* __restrict__ wf2 = reinterpret_cast<const float4*>(g_wf[2]);

    for (int tile = 0; tile < NTILES; ++tile) {
        const int base4 = tile * TILE_K4;

        // Load this thread's W slice for the tile into registers (once).
        float4 w0r[UNROLL], w1r[UNROLL], w2r[UNROLL];
#pragma unroll
        for (int i = 0; i < UNROLL; ++i) {
            int idx = base4 + i * THREADS_MAIN + tid;
            w0r[i] = wf0[idx];
            w1r[i] = wf1[idx];
            w2r[i] = wf2[idx];
        }

        int lr = 0;
        for (int r = bid; r < BROWS; r += GRID_MAIN, ++lr) {
            const float4* __restrict__ xr = x4 + (size_t)r * K4 + base4;

            float a0 = 0.0f, a1 = 0.0f, a2 = 0.0f;
#pragma unroll
            for (int i = 0; i < UNROLL; ++i) {
                float4 xv = __ldcs(&xr[i * THREADS_MAIN + tid]);
                a0 += xv.x * w0r[i].x; a0 += xv.y * w0r[i].y;
                a0 += xv.z * w0r[i].z; a0 += xv.w * w0r[i].w;
                a1 += xv.x * w1r[i].x; a1 += xv.y * w1r[i].y;
                a1 += xv.z * w1r[i].z; a1 += xv.w * w1r[i].w;
                a2 += xv.x * w2r[i].x; a2 += xv.y * w2r[i].y;
                a2 += xv.z * w2r[i].z; a2 += xv.w * w2r[i].w;
            }

            // Warp reduction of the 3 accumulators.
#pragma unroll
            for (int off = 16; off > 0; off >>= 1) {
                a0 += __shfl_xor_sync(0xffffffffu, a0, off);
                a1 += __shfl_xor_sync(0xffffffffu, a1, off);
                a2 += __shfl_xor_sync(0xffffffffu, a2, off);
            }

            if (lane == 0) {
                if (tile == 0) {
                    part[lr][wid][0] = a0;
                    part[lr][wid][1] = a1;
                    part[lr][wid][2] = a2;
                } else {
                    part[lr][wid][0] += a0;
                    part[lr][wid][1] += a1;
                    part[lr][wid][2] += a2;
                }
            }
        }
    }

    __syncthreads();

    // Final cross-warp reduction + bias.  At most 27*3 = 81 outputs per block.
    const int nrows = (BROWS - 1 - bid) / GRID_MAIN + 1;
    for (int o = tid; o < nrows * 3; o += THREADS_MAIN) {
        int lr = o / 3;
        int j  = o - lr * 3;
        float s = 0.0f;
#pragma unroll
        for (int w = 0; w < NWARPS; ++w) s += part[lr][w][j];
        int row = bid + lr * GRID_MAIN;
        out[row * 3 + j] = s + (float)NPTS * __ldg(&bias[j]);
    }
}

// ---------------------------------------------------------------------------
// Harness entry point.  Inputs (metadata order): input f32[4096, 24576],
// weight f32[8192, 6], bias f32[3].  Output f32[4096, 3].
// ---------------------------------------------------------------------------
extern "C" void kernel_launch(void* const* d_in, const int* in_sizes, int n_in,
                              void* d_out, int out_size) {
    const float* x      = (const float*)d_in[0];
    const float* weight = (const float*)d_in[1];
    const float* bias   = (const float*)d_in[2];
    float*       out    = (float*)d_out;
    (void)in_sizes; (void)n_in; (void)out_size;

    symm_prep_kernel<<<(NPTS + 255) / 256, 256>>>(weight);
    symm_main_kernel<<<GRID_MAIN, THREADS_MAIN>>>(x, bias, out);
}

// round 2
// speedup vs baseline: 1.1760x; 1.1760x over previous
#include <cuda_runtime.h>

// Problem constants
#define NPTS        8192
#define BROWS       4096
#define KTOT        (NPTS * 3)            // 24576 floats per row
#define K4          (KTOT / 4)            // 6144 float4 per row

// Main kernel config
#define GRID_MAIN    152                  // one persistent CTA per SM
#define THREADS_MAIN 512
#define NWARPS       (THREADS_MAIN / 32)  // 16
#define NTILES       3
#define TILE_K4      (K4 / NTILES)        // 2048 float4 per tile
#define UNROLL       (TILE_K4 / THREADS_MAIN) // 4 float4 per thread per tile
#define MAX_LROWS    ((BROWS + GRID_MAIN - 1) / GRID_MAIN) // 27

// Precomputed flattened weights, SoA by output index j:
// g_wf[j][3n+i] = (M^T M)[j][i] for point n.  288 KB static device scratch.
__device__ float g_wf[3][KTOT];

__device__ __forceinline__ float softplusf(float x) {
    return fmaxf(x, 0.0f) + log1pf(expf(-fabsf(x)));
}

// ---------------------------------------------------------------------------
// Kernel 1: build W = M^T M per integration point, expand to SoA flat layout.
// ---------------------------------------------------------------------------
__global__ void symm_prep_kernel(const float* __restrict__ weight) {
    int n = blockIdx.x * blockDim.x + threadIdx.x;
    if (n >= NPTS) return;

    const float* w = weight + n * 6;
    float a = softplusf(w[0]);
    float b = w[1];
    float c = w[2];
    float d = softplusf(w[3]);
    float e = w[4];
    float f = softplusf(w[5]);

    float m00 = a * a;
    float m01 = a * b;
    float m02 = a * c;
    float m11 = b * b + d * d;
    float m12 = b * c + d * e;
    float m22 = c * c + e * e + f * f;

    int k = 3 * n;
    g_wf[0][k + 0] = m00; g_wf[0][k + 1] = m01; g_wf[0][k + 2] = m02;
    g_wf[1][k + 0] = m01; g_wf[1][k + 1] = m11; g_wf[1][k + 2] = m12;
    g_wf[2][k + 0] = m02; g_wf[2][k + 1] = m12; g_wf[2][k + 2] = m22;
}

// ---------------------------------------------------------------------------
// Kernel 2: out[b, j] = sum_k x[b, k] * g_wf[j][k] + NPTS * bias[j]
//
// Register-resident W per K-tile; R=2 row blocking for deep load MLP
// (8 LDG.128 in flight per thread) and interleaved shuffle chains.
// ---------------------------------------------------------------------------
__global__ void __launch_bounds__(THREADS_MAIN, 1)
symm_main_kernel(const float* __restrict__ x,
                 const float* __restrict__ bias,
                 float* __restrict__ out) {
    __shared__ float part[MAX_LROWS][NWARPS][3];

    const int tid  = threadIdx.x;
    const int wid  = tid >> 5;
    const int lane = tid & 31;
    const int bid  = blockIdx.x;

    const float4* __restrict__ x4  = reinterpret_cast<const float4*>(x);
    const float4* __restrict__ wf0 = reinterpret_cast<const float4*>(g_wf[0]);
    const float4* __restrict__ wf1 = reinterpret_cast<const float4*>(g_wf[1]);
    const float4* __restrict__ wf2 = reinterpret_cast<const float4*>(g_wf[2]);

    for (int tile = 0; tile < NTILES; ++tile) {
        const int base4 = tile * TILE_K4;

        // This thread's W slice for the tile, in registers.
        float4 w0r[UNROLL], w1r[UNROLL], w2r[UNROLL];
#pragma unroll
        for (int i = 0; i < UNROLL; ++i) {
            int idx = base4 + i * THREADS_MAIN + tid;
            w0r[i] = wf0[idx];
            w1r[i] = wf1[idx];
            w2r[i] = wf2[idx];
        }

        // R=2 row blocking.
        for (int p = 0; ; ++p) {
            const int r0 = bid + (2 * p) * GRID_MAIN;
            if (r0 >= BROWS) break;
            const int r1 = r0 + GRID_MAIN;
            const bool has_r1 = (r1 < BROWS);

            const float4* __restrict__ xr0 = x4 + (size_t)r0 * K4 + base4;
            const float4* __restrict__ xr1 = x4 + (size_t)(has_r1 ? r1 : r0) * K4 + base4;

            float a0 = 0.0f, a1 = 0.0f, a2 = 0.0f;   // row r0
            float b0 = 0.0f, b1 = 0.0f, b2 = 0.0f;   // row r1

            // Issue all 8 loads up front (independent), then FMA.
            float4 xv0[UNROLL], xv1[UNROLL];
#pragma unroll
            for (int i = 0; i < UNROLL; ++i) {
                xv0[i] = __ldcs(&xr0[i * THREADS_MAIN + tid]);
                xv1[i] = __ldcs(&xr1[i * THREADS_MAIN + tid]);
            }

#pragma unroll
            for (int i = 0; i < UNROLL; ++i) {
                a0 = fmaf(xv0[i].x, w0r[i].x, a0); a0 = fmaf(xv0[i].y, w0r[i].y, a0);
                a0 = fmaf(xv0[i].z, w0r[i].z, a0); a0 = fmaf(xv0[i].w, w0r[i].w, a0);
                a1 = fmaf(xv0[i].x, w1r[i].x, a1); a1 = fmaf(xv0[i].y, w1r[i].y, a1);
                a1 = fmaf(xv0[i].z, w1r[i].z, a1); a1 = fmaf(xv0[i].w, w1r[i].w, a1);
                a2 = fmaf(xv0[i].x, w2r[i].x, a2); a2 = fmaf(xv0[i].y, w2r[i].y, a2);
                a2 = fmaf(xv0[i].z, w2r[i].z, a2); a2 = fmaf(xv0[i].w, w2r[i].w, a2);

                b0 = fmaf(xv1[i].x, w0r[i].x, b0); b0 = fmaf(xv1[i].y, w0r[i].y, b0);
                b0 = fmaf(xv1[i].z, w0r[i].z, b0); b0 = fmaf(xv1[i].w, w0r[i].w, b0);
                b1 = fmaf(xv1[i].x, w1r[i].x, b1); b1 = fmaf(xv1[i].y, w1r[i].y, b1);
                b1 = fmaf(xv1[i].z, w1r[i].z, b1); b1 = fmaf(xv1[i].w, w1r[i].w, b1);
                b2 = fmaf(xv1[i].x, w2r[i].x, b2); b2 = fmaf(xv1[i].y, w2r[i].y, b2);
                b2 = fmaf(xv1[i].z, w2r[i].z, b2); b2 = fmaf(xv1[i].w, w2r[i].w, b2);
            }

            // Warp reductions: 6 independent chains, interleaved.
#pragma unroll
            for (int off = 16; off > 0; off >>= 1) {
                a0 += __shfl_xor_sync(0xffffffffu, a0, off);
                b0 += __shfl_xor_sync(0xffffffffu, b0, off);
                a1 += __shfl_xor_sync(0xffffffffu, a1, off);
                b1 += __shfl_xor_sync(0xffffffffu, b1, off);
                a2 += __shfl_xor_sync(0xffffffffu, a2, off);
                b2 += __shfl_xor_sync(0xffffffffu, b2, off);
            }

            if (lane == 0) {
                const int lr0 = 2 * p;
                if (tile == 0) {
                    part[lr0][wid][0] = a0;
                    part[lr0][wid][1] = a1;
                    part[lr0][wid][2] = a2;
                    if (has_r1) {
                        part[lr0 + 1][wid][0] = b0;
                        part[lr0 + 1][wid][1] = b1;
                        part[lr0 + 1][wid][2] = b2;
                    }
                } else {
                    part[lr0][wid][0] += a0;
                    part[lr0][wid][1] += a1;
                    part[lr0][wid][2] += a2;
                    if (has_r1) {
                        part[lr0 + 1][wid][0] += b0;
                        part[lr0 + 1][wid][1] += b1;
                        part[lr0 + 1][wid][2] += b2;
                    }
                }
            }
        }
    }

    __syncthreads();

    // Final cross-warp reduction + bias.
    const int nrows = (BROWS - 1 - bid) / GRID_MAIN + 1;
    for (int o = tid; o < nrows * 3; o += THREADS_MAIN) {
        int lr = o / 3;
        int j  = o - lr * 3;
        float s = 0.0f;
#pragma unroll
        for (int w = 0; w < NWARPS; ++w) s += part[lr][w][j];
        int row = bid + lr * GRID_MAIN;
        out[row * 3 + j] = s + (float)NPTS * __ldg(&bias[j]);
    }
}

// ---------------------------------------------------------------------------
extern "C" void kernel_launch(void* const* d_in, const int* in_sizes, int n_in,
                              void* d_out, int out_size) {
    const float* x      = (const float*)d_in[0];
    const float* weight = (const float*)d_in[1];
    const float* bias   = (const float*)d_in[2];
    float*       out    = (float*)d_out;
    (void)in_sizes; (void)n_in; (void)out_size;

    symm_prep_kernel<<<(NPTS + 255) / 256, 256>>>(weight);
    symm_main_kernel<<<GRID_MAIN, THREADS_MAIN>>>(x, bias, out);
}

// round 3
// speedup vs baseline: 1.1805x; 1.0038x over previous
#include <cuda_runtime.h>

// Problem constants
#define NPTS        8192
#define BROWS       4096
#define KTOT        (NPTS * 3)            // 24576 floats per row
#define K4          (KTOT / 4)            // 6144 float4 per row

// Main kernel config
#define GRID_MAIN    152                  // one persistent CTA per SM
#define THREADS_MAIN 512
#define NWARPS       (THREADS_MAIN / 32)  // 16
#define NTILES       4
#define TILE_K4      (K4 / NTILES)        // 1536 float4 per tile
#define UNROLL       (TILE_K4 / THREADS_MAIN) // 3 float4 per thread per tile
#define MAX_LROWS    ((BROWS + GRID_MAIN - 1) / GRID_MAIN) // 27

// Precomputed flattened weights, SoA by output index j. 288 KB device scratch.
__device__ float g_wf[3][KTOT];

__device__ __forceinline__ float softplusf(float x) {
    return fmaxf(x, 0.0f) + log1pf(expf(-fabsf(x)));
}

// ---------------------------------------------------------------------------
// Kernel 1: build W = M^T M per integration point, expand to SoA flat layout.
// ---------------------------------------------------------------------------
__global__ void symm_prep_kernel(const float* __restrict__ weight) {
    int n = blockIdx.x * blockDim.x + threadIdx.x;
    if (n >= NPTS) return;

    const float* w = weight + n * 6;
    float a = softplusf(w[0]);
    float b = w[1];
    float c = w[2];
    float d = softplusf(w[3]);
    float e = w[4];
    float f = softplusf(w[5]);

    float m00 = a * a;
    float m01 = a * b;
    float m02 = a * c;
    float m11 = b * b + d * d;
    float m12 = b * c + d * e;
    float m22 = c * c + e * e + f * f;

    int k = 3 * n;
    g_wf[0][k + 0] = m00; g_wf[0][k + 1] = m01; g_wf[0][k + 2] = m02;
    g_wf[1][k + 0] = m01; g_wf[1][k + 1] = m11; g_wf[1][k + 2] = m12;
    g_wf[2][k + 0] = m02; g_wf[2][k + 1] = m12; g_wf[2][k + 2] = m22;
}

// ---------------------------------------------------------------------------
// Kernel 2: register-resident W per K-tile, R=2 row pairs, software-pipelined
// double-buffered loads so the LSU never drains during FMA/shuffle phases.
// ---------------------------------------------------------------------------
struct PairBuf {
    float4 v0[UNROLL];
    float4 v1[UNROLL];
};

__device__ __forceinline__ void load_pair(PairBuf& buf,
                                          const float4* __restrict__ x4,
                                          int r0, int r1, int base4, int tid) {
    const float4* __restrict__ xr0 = x4 + (size_t)r0 * K4 + base4;
    const float4* __restrict__ xr1 = x4 + (size_t)r1 * K4 + base4;
#pragma unroll
    for (int i = 0; i < UNROLL; ++i) {
        buf.v0[i] = __ldcs(&xr0[i * THREADS_MAIN + tid]);
        buf.v1[i] = __ldcs(&xr1[i * THREADS_MAIN + tid]);
    }
}

__global__ void __launch_bounds__(THREADS_MAIN, 1)
symm_main_kernel(const float* __restrict__ x,
                 const float* __restrict__ bias,
                 float* __restrict__ out) {
    __shared__ float part[MAX_LROWS][NWARPS][3];

    const int tid  = threadIdx.x;
    const int wid  = tid >> 5;
    const int lane = tid & 31;
    const int bid  = blockIdx.x;

    const float4* __restrict__ x4  = reinterpret_cast<const float4*>(x);
    const float4* __restrict__ wf0 = reinterpret_cast<const float4*>(g_wf[0]);
    const float4* __restrict__ wf1 = reinterpret_cast<const float4*>(g_wf[1]);
    const float4* __restrict__ wf2 = reinterpret_cast<const float4*>(g_wf[2]);

    const int nrows  = (BROWS - 1 - bid) / GRID_MAIN + 1;   // 26 or 27
    const int npairs = (nrows + 1) / 2;

    // Row indices for pair p: r0 = bid + 2p*GRID, r1 = r0 + GRID (clamped).
    for (int tile = 0; tile < NTILES; ++tile) {
        const int base4 = tile * TILE_K4;

        // W slice for this tile, registers.
        float4 w0r[UNROLL], w1r[UNROLL], w2r[UNROLL];
#pragma unroll
        for (int i = 0; i < UNROLL; ++i) {
            int idx = base4 + i * THREADS_MAIN + tid;
            w0r[i] = wf0[idx];
            w1r[i] = wf1[idx];
            w2r[i] = wf2[idx];
        }

        PairBuf A, B;

        // Prologue: load pair 0.
        {
            int r0 = bid;
            int r1 = (r0 + GRID_MAIN < BROWS) ? r0 + GRID_MAIN : r0;
            load_pair(A, x4, r0, r1, base4, tid);
        }

        // Process-one-pair macro body as a lambda (stays in registers).
        auto process = [&](const PairBuf& buf, int p) {
            const int  r1    = bid + (2 * p + 1) * GRID_MAIN;
            const bool has_r1 = (r1 < BROWS);

            float a0 = 0.0f, a1 = 0.0f, a2 = 0.0f;
            float b0 = 0.0f, b1 = 0.0f, b2 = 0.0f;
#pragma unroll
            for (int i = 0; i < UNROLL; ++i) {
                a0 = fmaf(buf.v0[i].x, w0r[i].x, a0); a0 = fmaf(buf.v0[i].y, w0r[i].y, a0);
                a0 = fmaf(buf.v0[i].z, w0r[i].z, a0); a0 = fmaf(buf.v0[i].w, w0r[i].w, a0);
                a1 = fmaf(buf.v0[i].x, w1r[i].x, a1); a1 = fmaf(buf.v0[i].y, w1r[i].y, a1);
                a1 = fmaf(buf.v0[i].z, w1r[i].z, a1); a1 = fmaf(buf.v0[i].w, w1r[i].w, a1);
                a2 = fmaf(buf.v0[i].x, w2r[i].x, a2); a2 = fmaf(buf.v0[i].y, w2r[i].y, a2);
                a2 = fmaf(buf.v0[i].z, w2r[i].z, a2); a2 = fmaf(buf.v0[i].w, w2r[i].w, a2);

                b0 = fmaf(buf.v1[i].x, w0r[i].x, b0); b0 = fmaf(buf.v1[i].y, w0r[i].y, b0);
                b0 = fmaf(buf.v1[i].z, w0r[i].z, b0); b0 = fmaf(buf.v1[i].w, w0r[i].w, b0);
                b1 = fmaf(buf.v1[i].x, w1r[i].x, b1); b1 = fmaf(buf.v1[i].y, w1r[i].y, b1);
                b1 = fmaf(buf.v1[i].z, w1r[i].z, b1); b1 = fmaf(buf.v1[i].w, w1r[i].w, b1);
                b2 = fmaf(buf.v1[i].x, w2r[i].x, b2); b2 = fmaf(buf.v1[i].y, w2r[i].y, b2);
                b2 = fmaf(buf.v1[i].z, w2r[i].z, b2); b2 = fmaf(buf.v1[i].w, w2r[i].w, b2);
            }

#pragma unroll
            for (int off = 16; off > 0; off >>= 1) {
                a0 += __shfl_xor_sync(0xffffffffu, a0, off);
                b0 += __shfl_xor_sync(0xffffffffu, b0, off);
                a1 += __shfl_xor_sync(0xffffffffu, a1, off);
                b1 += __shfl_xor_sync(0xffffffffu, b1, off);
                a2 += __shfl_xor_sync(0xffffffffu, a2, off);
                b2 += __shfl_xor_sync(0xffffffffu, b2, off);
            }

            if (lane == 0) {
                const int lr0 = 2 * p;
                if (tile == 0) {
                    part[lr0][wid][0] = a0;
                    part[lr0][wid][1] = a1;
                    part[lr0][wid][2] = a2;
                    if (has_r1) {
                        part[lr0 + 1][wid][0] = b0;
                        part[lr0 + 1][wid][1] = b1;
                        part[lr0 + 1][wid][2] = b2;
                    }
                } else {
                    part[lr0][wid][0] += a0;
                    part[lr0][wid][1] += a1;
                    part[lr0][wid][2] += a2;
                    if (has_r1) {
                        part[lr0 + 1][wid][0] += b0;
                        part[lr0 + 1][wid][1] += b1;
                        part[lr0 + 1][wid][2] += b2;
                    }
                }
            }
        };

        auto prefetch = [&](PairBuf& buf, int p) {
            int r0 = bid + (2 * p) * GRID_MAIN;
            int r1 = r0 + GRID_MAIN;
            if (r1 >= BROWS) r1 = r0;
            load_pair(buf, x4, r0, r1, base4, tid);
        };

        // Ping-pong pipeline, unrolled by 2 so buffers stay in registers.
        for (int p = 0; p < npairs; p += 2) {
            if (p + 1 < npairs) prefetch(B, p + 1);
            process(A, p);
            if (p + 1 < npairs) {
                if (p + 2 < npairs) prefetch(A, p + 2);
                process(B, p + 1);
            }
        }
    }

    __syncthreads();

    // Final cross-warp reduction + bias.
    for (int o = tid; o < nrows * 3; o += THREADS_MAIN) {
        int lr = o / 3;
        int j  = o - lr * 3;
        float s = 0.0f;
#pragma unroll
        for (int w = 0; w < NWARPS; ++w) s += part[lr][w][j];
        int row = bid + lr * GRID_MAIN;
        out[row * 3 + j] = s + (float)NPTS * __ldg(&bias[j]);
    }
}

// ---------------------------------------------------------------------------
extern "C" void kernel_launch(void* const* d_in, const int* in_sizes, int n_in,
                              void* d_out, int out_size) {
    const float* x      = (const float*)d_in[0];
    const float* weight = (const float*)d_in[1];
    const float* bias   = (const float*)d_in[2];
    float*       out    = (float*)d_out;
    (void)in_sizes; (void)n_in; (void)out_size;

    symm_prep_kernel<<<(NPTS + 255) / 256, 256>>>(weight);
    symm_main_kernel<<<GRID_MAIN, THREADS_MAIN>>>(x, bias, out);
}